// round 5
// baseline (speedup 1.0000x reference)
#include <cuda_runtime.h>
#include <cuda_bf16.h>

typedef unsigned long long u64;

#define NBH 1024   // B*H
#define TT  4
#define DK  128
#define DV  256
#define SLOT 17    // u64 per redD row (16 + 1 pad -> 136B row, conflict-free)
#define SROW 36    // floats per sumsD row (32 + 4 pad)

// ---- packed f32x2 helpers (Blackwell sm_103a) ----
__device__ __forceinline__ u64 pk2(float x, float y){
    u64 r; asm("mov.b64 %0, {%1,%2};" : "=l"(r) : "f"(x), "f"(y)); return r;
}
__device__ __forceinline__ u64 pk1(float x){ return pk2(x, x); }
__device__ __forceinline__ void up2(u64 a, float& x, float& y){
    asm("mov.b64 {%0,%1}, %2;" : "=f"(x), "=f"(y) : "l"(a));
}
__device__ __forceinline__ u64 fma2(u64 a, u64 b, u64 c){
    u64 d; asm("fma.rn.f32x2 %0, %1, %2, %3;" : "=l"(d) : "l"(a), "l"(b), "l"(c)); return d;
}
__device__ __forceinline__ u64 mul2(u64 a, u64 b){
    u64 d; asm("mul.rn.f32x2 %0, %1, %2;" : "=l"(d) : "l"(a), "l"(b)); return d;
}

// Gram-decomposed gated delta rule:
//   S'_{t-1}.k_t = S0.k_t + sum_{s<t} (k_s.k_t) d'_s
//   out_t = c_t*(S0.q_t + sum_{s<=t} (k_s.q_t) d'_s)
//   d'_t  = beta_t*(v_t/c_t - m_t),  m_t = S0.k_t + sum_{s<t} K_st d'_s
//   S_out = c_3*(S0 + sum_t k_t d'_t)
// => ONE sweep over register state for all 8 dots, ONE smem reduction
//    (2 barriers) for the whole kernel, then pure-local math + updates.
__global__ __launch_bounds__(256, 4)
void gdn_step_kernel(const float* __restrict__ q, const float* __restrict__ k,
                     const float* __restrict__ v, const float* __restrict__ g,
                     const float* __restrict__ beta, const float* __restrict__ s0,
                     float* __restrict__ out, float* __restrict__ sout)
{
    const int bh    = blockIdx.x >> 2;
    const int quad  = blockIdx.x & 3;
    const int vbase = quad * 64;
    const int tid   = threadIdx.x;
    const int cg    = tid & 15;    // column group (4 cols)
    const int rg    = tid >> 4;    // row group (8 rows)
    const int k0    = rg * 8;
    const int v0    = vbase + cg * 4;

    __shared__ __align__(16) float qs[TT * DK];
    __shared__ __align__(16) float ks[TT * DK];
    __shared__ __align__(16) float vs[TT * 64];
    __shared__ float gs[TT], bs[TT];
    __shared__ u64   redD[256 * SLOT];     // 8 dot partials per thread (16 u64)
    __shared__ float redG[256];            // gram partials (pair = cg)
    __shared__ float sumsD[16 * SROW];     // reduced dots per cg (32 floats)
    __shared__ __align__(16) float gram[16];

    // ---- front-batched state load: 8 x LDG.128 streaming, coalesced ----
    const size_t sbase = (size_t)bh * (DK * DV);
    ulonglong2 S[8];
#pragma unroll
    for (int kk = 0; kk < 8; kk++){
        float4 f = __ldcs((const float4*)(s0 + sbase + (size_t)(k0 + kk) * DV + v0));
        S[kk].x = pk2(f.x, f.y);
        S[kk].y = pk2(f.z, f.w);
    }

    // ---- stage q/k/v/g/beta into smem ----
    {
        const int qb = bh * (TT * DK);
        for (int i = tid; i < TT * DK; i += 256){ qs[i] = q[qb + i]; ks[i] = k[qb + i]; }
        const int vb = bh * (TT * DV);
        {
            int t = tid >> 6, j = tid & 63;      // 256 = 4*64 exactly
            vs[tid] = v[vb + t * DV + vbase + j];
        }
        if (tid < TT){ gs[tid] = g[bh * TT + tid]; bs[tid] = beta[bh * TT + tid]; }
    }
    __syncthreads();

    // ---- stage1: ONE sweep over S0 computes all 8 dots (k_t, q_t, t=0..3)
#pragma unroll
    for (int t = 0; t < TT; t++){
        float4 kA = *(const float4*)&ks[t * DK + k0];
        float4 kB = *(const float4*)&ks[t * DK + k0 + 4];
        float4 qA = *(const float4*)&qs[t * DK + k0];
        float4 qB = *(const float4*)&qs[t * DK + k0 + 4];
        float kf[8] = {kA.x, kA.y, kA.z, kA.w, kB.x, kB.y, kB.z, kB.w};
        float qf[8] = {qA.x, qA.y, qA.z, qA.w, qB.x, qB.y, qB.z, qB.w};
        u64 ax = 0ull, ay = 0ull, ox = 0ull, oy = 0ull;
#pragma unroll
        for (int kk = 0; kk < 8; kk++){
            u64 kt2 = pk1(kf[kk]);
            u64 qt2 = pk1(qf[kk]);
            ax = fma2(S[kk].x, kt2, ax);
            ay = fma2(S[kk].y, kt2, ay);
            ox = fma2(S[kk].x, qt2, ox);
            oy = fma2(S[kk].y, qt2, oy);
        }
        u64* r = &redD[tid * SLOT + t * 4];
        r[0] = ax; r[1] = ay; r[2] = ox; r[3] = oy;
    }
    // gram partial: thread's cg selects one of 16 pairs, dot over its 8 rows
    {
        // pairs 0-5: k_s.k_t (01,02,03,12,13,23); 6-15: k_s.q_t (00,01,02,03,11,12,13,22,23,33)
        const int psA[16] = {0,0,0,1,1,2, 0,0,0,0,1,1,1,2,2,3};
        const int ptA[16] = {1,2,3,2,3,3, 0,1,2,3,1,2,3,2,3,3};
        const float* aa = &ks[psA[cg] * DK + k0];
        const float* bb = (cg < 6 ? &ks[ptA[cg] * DK + k0] : &qs[ptA[cg] * DK + k0]);
        float4 a0 = *(const float4*)aa,      a1 = *(const float4*)(aa + 4);
        float4 b0 = *(const float4*)bb,      b1 = *(const float4*)(bb + 4);
        float s = a0.x*b0.x + a0.y*b0.y + a0.z*b0.z + a0.w*b0.w
                + a1.x*b1.x + a1.y*b1.y + a1.z*b1.z + a1.w*b1.w;
        redG[tid] = s;
    }
    __syncthreads();

    // ---- stage2: transposed reduce over 16 row-groups ----
    {
        const float* rf = (const float*)redD;   // row stride = 2*SLOT floats
#pragma unroll
        for (int rep = 0; rep < 2; rep++){
            int idx = tid + rep * 256;
            int c2  = idx & 15;
            int f   = idx >> 4;      // 0..31
            float s = 0.0f;
#pragma unroll
            for (int r2 = 0; r2 < 16; r2++)
                s += rf[(r2 * 16 + c2) * (2 * SLOT) + f];
            sumsD[c2 * SROW + f] = s;
        }
        if (tid < 16){
            float s = 0.0f;
#pragma unroll
            for (int r2 = 0; r2 < 16; r2++)
                s += redG[r2 * 16 + tid];
            gram[tid] = s;
        }
    }
    __syncthreads();

    // ---- stage3: local recurrence over 4 steps (tiny), outputs, updates ----
    float4 G0 = *(const float4*)&gram[0];    // kk: 01,02,03,12
    float4 G1 = *(const float4*)&gram[4];    // kk: 13,23 ; kq: 00,01
    float4 G2 = *(const float4*)&gram[8];    // kq: 02,03,11,12
    float4 G3 = *(const float4*)&gram[12];   // kq: 13,22,23,33

    float a0 = __expf(gs[0]), a1 = __expf(gs[1]), a2 = __expf(gs[2]), a3 = __expf(gs[3]);
    float c0 = a0, c1 = c0*a1, c2 = c1*a2, c3 = c2*a3;
    float cc[4] = {c0, c1, c2, c3};

    u64 dPx[4], dPy[4];
    const float* sp = &sumsD[cg * SROW];

#pragma unroll
    for (int t = 0; t < TT; t++){
        float4 sk = *(const float4*)&sp[t * 8];        // S0.k_t (4 cols)
        float4 sq = *(const float4*)&sp[t * 8 + 4];    // S0.q_t
        u64 mx = pk2(sk.x, sk.y), my = pk2(sk.z, sk.w);
        // m += K_st * d'_s  (s < t)
        if (t == 1){ u64 gk = pk1(G0.x); mx = fma2(gk, dPx[0], mx); my = fma2(gk, dPy[0], my); }
        if (t == 2){
            u64 g02 = pk1(G0.y), g12 = pk1(G0.w);
            mx = fma2(g02, dPx[0], mx); my = fma2(g02, dPy[0], my);
            mx = fma2(g12, dPx[1], mx); my = fma2(g12, dPy[1], my);
        }
        if (t == 3){
            u64 g03 = pk1(G0.z), g13 = pk1(G1.x), g23 = pk1(G1.y);
            mx = fma2(g03, dPx[0], mx); my = fma2(g03, dPy[0], my);
            mx = fma2(g13, dPx[1], mx); my = fma2(g13, dPy[1], my);
            mx = fma2(g23, dPx[2], mx); my = fma2(g23, dPy[2], my);
        }
        // d'_t = beta*(v/c - m)
        float4 vv = *(const float4*)&vs[t * 64 + cg * 4];
        float bi = bs[t];
        float ic = 1.0f / cc[t];
        u64 bic2 = pk1(bi * ic);
        u64 nb2  = pk1(-bi);
        dPx[t] = fma2(mx, nb2, mul2(pk2(vv.x, vv.y), bic2));
        dPy[t] = fma2(my, nb2, mul2(pk2(vv.z, vv.w), bic2));

        // out_t = c_t*(S0.q_t + sum_{s<=t} (k_s.q_t) d'_s)
        u64 ox = pk2(sq.x, sq.y), oy = pk2(sq.z, sq.w);
        if (t == 0){ u64 gq = pk1(G1.z); ox = fma2(gq, dPx[0], ox); oy = fma2(gq, dPy[0], oy); }
        if (t == 1){
            u64 q01 = pk1(G1.w), q11 = pk1(G2.z);
            ox = fma2(q01, dPx[0], ox); oy = fma2(q01, dPy[0], oy);
            ox = fma2(q11, dPx[1], ox); oy = fma2(q11, dPy[1], oy);
        }
        if (t == 2){
            u64 q02 = pk1(G2.x), q12 = pk1(G2.w), q22 = pk1(G3.y);
            ox = fma2(q02, dPx[0], ox); oy = fma2(q02, dPy[0], oy);
            ox = fma2(q12, dPx[1], ox); oy = fma2(q12, dPy[1], oy);
            ox = fma2(q22, dPx[2], ox); oy = fma2(q22, dPy[2], oy);
        }
        if (t == 3){
            u64 q03 = pk1(G2.y), q13 = pk1(G3.x), q23 = pk1(G3.z), q33 = pk1(G3.w);
            ox = fma2(q03, dPx[0], ox); oy = fma2(q03, dPy[0], oy);
            ox = fma2(q13, dPx[1], ox); oy = fma2(q13, dPy[1], oy);
            ox = fma2(q23, dPx[2], ox); oy = fma2(q23, dPy[2], oy);
            ox = fma2(q33, dPx[3], ox); oy = fma2(q33, dPy[3], oy);
        }
        if (rg == 0){
            u64 ct2 = pk1(cc[t]);
            ulonglong2 o;
            o.x = mul2(ox, ct2);
            o.y = mul2(oy, ct2);
            *(ulonglong2*)(out + (size_t)(bh * TT + t) * DV + v0) = o;
        }
    }

    // ---- apply all rank-1 updates: S' += sum_t k_t d'_t ----
#pragma unroll
    for (int t = 0; t < TT; t++){
        float4 kA = *(const float4*)&ks[t * DK + k0];
        float4 kB = *(const float4*)&ks[t * DK + k0 + 4];
        float kf[8] = {kA.x, kA.y, kA.z, kA.w, kB.x, kB.y, kB.z, kB.w};
#pragma unroll
        for (int kk = 0; kk < 8; kk++){
            u64 kt2 = pk1(kf[kk]);
            S[kk].x = fma2(kt2, dPx[t], S[kk].x);
            S[kk].y = fma2(kt2, dPy[t], S[kk].y);
        }
    }

    // ---- final state writeback: state = c3 * S', streaming stores ----
    u64 c32 = pk1(c3);
#pragma unroll
    for (int kk = 0; kk < 8; kk++){
        u64 wx = mul2(S[kk].x, c32);
        u64 wy = mul2(S[kk].y, c32);
        float4 f;
        up2(wx, f.x, f.y);
        up2(wy, f.z, f.w);
        __stcs((float4*)(sout + sbase + (size_t)(k0 + kk) * DV + v0), f);
    }
}

extern "C" void kernel_launch(void* const* d_in, const int* in_sizes, int n_in,
                              void* d_out, int out_size)
{
    const float* q    = (const float*)d_in[0];
    const float* k    = (const float*)d_in[1];
    const float* v    = (const float*)d_in[2];
    const float* g    = (const float*)d_in[3];
    const float* beta = (const float*)d_in[4];
    const float* s0   = (const float*)d_in[5];
    float* out  = (float*)d_out;
    float* sout = out + (size_t)NBH * TT * DV;   // state follows the T outputs

    gdn_step_kernel<<<NBH * 4, 256>>>(q, k, v, g, beta, s0, out, sout);
}